// round 5
// baseline (speedup 1.0000x reference)
#include <cuda_runtime.h>
#include <cstdint>
#include <cstddef>

#define NPTS 262144
#define NPLANES 128
#define D 64
#define TWOD 128

typedef unsigned long long u64;

// packed f32x2 helpers (sm_103a)
#define FMA_F32X2(d, a, b, c) \
    asm("fma.rn.f32x2 %0, %1, %2, %3;" : "=l"(d) : "l"(a), "l"(b), "l"(c))
#define DUP_F32X2(d, s) \
    asm("mov.b64 %0, {%1, %1};" : "=l"(d) : "r"(s))
#define UNPACK_F32X2(lo, hi, in) \
    asm("mov.b64 {%0, %1}, %2;" : "=r"(lo), "=r"(hi) : "l"(in))

// scratch (allocation-free rule: __device__ globals)
__device__ float g_h2[(size_t)NPTS * D];     // post-ReLU fc2 features, [N][64]
__device__ float g_scores[NPTS];             // post-ReLU fc3 scores

// ---------------------------------------------------------------------------
// Kernel A: fused per-point MLP (fc1+BN+ReLU -> fc2+BN+ReLU -> fc3+ReLU)
// 64 points per block, 256 threads, each thread computes a 4x4 (point x chan)
// tile with point-pair-packed fma.rn.f32x2 (2 IEEE fp32 FMAs per issue).
// ---------------------------------------------------------------------------
constexpr int BM  = 64;
constexpr int ATH = 256;
constexpr int FTS = 66;                       // EVEN stride -> 8B-aligned v2 loads
constexpr int OFF_W2 = TWOD * D;              // 8192
constexpr int OFF_FT = OFF_W2 + D * D;        // 12288
constexpr int OFF_H1 = OFF_FT + TWOD * FTS;   // 12288 + 8448
constexpr int SMEM_A_FLOATS = OFF_H1 + D * FTS;
constexpr size_t SMEM_A_BYTES = (size_t)SMEM_A_FLOATS * sizeof(float); // ~97.5 KB

__global__ void __launch_bounds__(ATH, 2)
mlp_kernel(const float* __restrict__ feat, const float* __restrict__ fgeo,
           const float* __restrict__ w1, const float* __restrict__ b1,
           const float* __restrict__ g1, const float* __restrict__ be1,
           const float* __restrict__ m1, const float* __restrict__ v1,
           const float* __restrict__ w2, const float* __restrict__ b2,
           const float* __restrict__ g2, const float* __restrict__ be2,
           const float* __restrict__ m2, const float* __restrict__ v2,
           const float* __restrict__ w3, const float* __restrict__ b3)
{
    extern __shared__ float sm[];
    float* sW1  = sm;             // [128][64]
    float* sW2  = sm + OFF_W2;    // [64][64]
    float* sFT  = sm + OFF_FT;    // fT[k][p], stride 66
    float* sH1T = sm + OFF_H1;    // h1T[k][p], stride 66

    const int t  = threadIdx.x;
    const int n0 = blockIdx.x * BM;

    for (int i = t; i < TWOD * D; i += ATH) sW1[i] = w1[i];
    for (int i = t; i < D * D;    i += ATH) sW2[i] = w2[i];
    for (int i = t; i < BM * TWOD; i += ATH) {
        int p = i >> 7, c = i & 127;
        float v = (c < D) ? feat[(size_t)(n0 + p) * D + c]
                          : fgeo[(size_t)(n0 + p) * D + (c - D)];
        sFT[c * FTS + p] = v;
    }

    const int tj = t & 15, tp = t >> 4;
    const int j0 = tj * 4, p0 = tp * 4;

    // folded BN constants for this thread's 4 output channels
    float s1v[4], t1v[4], s2v[4], t2v[4], w3v[4];
#pragma unroll
    for (int jj = 0; jj < 4; jj++) {
        int j = j0 + jj;
        float sc = g1[j] * rsqrtf(v1[j] + 1e-5f);
        s1v[jj] = sc; t1v[jj] = (b1[j] - m1[j]) * sc + be1[j];
        sc = g2[j] * rsqrtf(v2[j] + 1e-5f);
        s2v[jj] = sc; t2v[jj] = (b2[j] - m2[j]) * sc + be2[j];
        w3v[jj] = w3[j];
    }
    __syncthreads();

    // ---- fc1: [64pts x 128] @ [128 x 64], point-pair packed ----
    // accp[pp][jj]: points (p0+2pp, p0+2pp+1), channel j0+jj
    u64 accp[2][4];
#pragma unroll
    for (int pp = 0; pp < 2; pp++)
#pragma unroll
        for (int jj = 0; jj < 4; jj++) accp[pp][jj] = 0ull;

#pragma unroll 4
    for (int k = 0; k < TWOD; k++) {
        float4 wv = *(const float4*)&sW1[k * D + j0];
        u64 f01 = *(const u64*)&sFT[k * FTS + p0];       // (f0,f1)
        u64 f23 = *(const u64*)&sFT[k * FTS + p0 + 2];   // (f2,f3)
        u64 wd0, wd1, wd2, wd3;
        DUP_F32X2(wd0, __float_as_uint(wv.x));
        DUP_F32X2(wd1, __float_as_uint(wv.y));
        DUP_F32X2(wd2, __float_as_uint(wv.z));
        DUP_F32X2(wd3, __float_as_uint(wv.w));
        FMA_F32X2(accp[0][0], f01, wd0, accp[0][0]);
        FMA_F32X2(accp[0][1], f01, wd1, accp[0][1]);
        FMA_F32X2(accp[0][2], f01, wd2, accp[0][2]);
        FMA_F32X2(accp[0][3], f01, wd3, accp[0][3]);
        FMA_F32X2(accp[1][0], f23, wd0, accp[1][0]);
        FMA_F32X2(accp[1][1], f23, wd1, accp[1][1]);
        FMA_F32X2(accp[1][2], f23, wd2, accp[1][2]);
        FMA_F32X2(accp[1][3], f23, wd3, accp[1][3]);
    }
#pragma unroll
    for (int pp = 0; pp < 2; pp++)
#pragma unroll
        for (int jj = 0; jj < 4; jj++) {
            unsigned lo, hi;
            UNPACK_F32X2(lo, hi, accp[pp][jj]);
            float a0 = __uint_as_float(lo), a1 = __uint_as_float(hi);
            float h0 = fmaxf(a0 * s1v[jj] + t1v[jj], 0.f);
            float h1 = fmaxf(a1 * s1v[jj] + t1v[jj], 0.f);
            sH1T[(j0 + jj) * FTS + p0 + 2 * pp]     = h0;  // transposed for fc2
            sH1T[(j0 + jj) * FTS + p0 + 2 * pp + 1] = h1;
        }
    __syncthreads();

    // ---- fc2: [64pts x 64] @ [64 x 64], point-pair packed ----
    u64 acc2p[2][4];
#pragma unroll
    for (int pp = 0; pp < 2; pp++)
#pragma unroll
        for (int jj = 0; jj < 4; jj++) acc2p[pp][jj] = 0ull;

#pragma unroll 4
    for (int k = 0; k < D; k++) {
        float4 wv = *(const float4*)&sW2[k * D + j0];
        u64 f01 = *(const u64*)&sH1T[k * FTS + p0];
        u64 f23 = *(const u64*)&sH1T[k * FTS + p0 + 2];
        u64 wd0, wd1, wd2, wd3;
        DUP_F32X2(wd0, __float_as_uint(wv.x));
        DUP_F32X2(wd1, __float_as_uint(wv.y));
        DUP_F32X2(wd2, __float_as_uint(wv.z));
        DUP_F32X2(wd3, __float_as_uint(wv.w));
        FMA_F32X2(acc2p[0][0], f01, wd0, acc2p[0][0]);
        FMA_F32X2(acc2p[0][1], f01, wd1, acc2p[0][1]);
        FMA_F32X2(acc2p[0][2], f01, wd2, acc2p[0][2]);
        FMA_F32X2(acc2p[0][3], f01, wd3, acc2p[0][3]);
        FMA_F32X2(acc2p[1][0], f23, wd0, acc2p[1][0]);
        FMA_F32X2(acc2p[1][1], f23, wd1, acc2p[1][1]);
        FMA_F32X2(acc2p[1][2], f23, wd2, acc2p[1][2]);
        FMA_F32X2(acc2p[1][3], f23, wd3, acc2p[1][3]);
    }

    // bn2 + relu, write h2, accumulate fc3 partial dot
    float h2v[4][4];   // [point ii][chan jj]
#pragma unroll
    for (int pp = 0; pp < 2; pp++)
#pragma unroll
        for (int jj = 0; jj < 4; jj++) {
            unsigned lo, hi;
            UNPACK_F32X2(lo, hi, acc2p[pp][jj]);
            h2v[2 * pp][jj]     = fmaxf(__uint_as_float(lo) * s2v[jj] + t2v[jj], 0.f);
            h2v[2 * pp + 1][jj] = fmaxf(__uint_as_float(hi) * s2v[jj] + t2v[jj], 0.f);
        }
    float psum[4];
#pragma unroll
    for (int ii = 0; ii < 4; ii++) {
        float4 hv = make_float4(h2v[ii][0], h2v[ii][1], h2v[ii][2], h2v[ii][3]);
        *(float4*)&g_h2[(size_t)(n0 + p0 + ii) * D + j0] = hv;
        psum[ii] = hv.x * w3v[0] + hv.y * w3v[1] + hv.z * w3v[2] + hv.w * w3v[3];
    }
    // reduce fc3 partials across the 16 threads sharing this point group
#pragma unroll
    for (int ofs = 8; ofs >= 1; ofs >>= 1)
#pragma unroll
        for (int ii = 0; ii < 4; ii++)
            psum[ii] += __shfl_down_sync(0xffffffffu, psum[ii], ofs, 16);
    if (tj == 0) {
        float bb = b3[0];
#pragma unroll
        for (int ii = 0; ii < 4; ii++)
            g_scores[n0 + p0 + ii] = fmaxf(psum[ii] + bb, 0.f);
    }
}

// ---------------------------------------------------------------------------
// Kernel B: per-plane masks + output streaming + masked max-pool
// 1024 points per block (4 per thread, contiguous -> float4 stores), 256 threads.
// ---------------------------------------------------------------------------
constexpr int BTH = 256;
constexpr int PB  = 1024;

__global__ void __launch_bounds__(BTH)
mask_pool_kernel(const float* __restrict__ xyz, const float* __restrict__ centers,
                 const float* __restrict__ pcen, const float* __restrict__ pnrm,
                 const float* __restrict__ pmin, const float* __restrict__ pmax,
                 float* __restrict__ out)
{
    __shared__ float sNx[NPLANES], sNy[NPLANES], sNz[NPLANES], sOf[NPLANES];
    __shared__ float sMnx[NPLANES], sMny[NPLANES], sMnz[NPLANES];
    __shared__ float sMxx[NPLANES], sMxy[NPLANES], sMxz[NPLANES];
    __shared__ float sCx[PB], sCy[PB], sCz[PB], sS[PB];
    __shared__ float sRed[2 * 8 * 64];    // [on/off][warp][d]

    const int t = threadIdx.x;
    const int warp = t >> 5, lane = t & 31;
    const int n0 = blockIdx.x * PB;

    if (t < NPLANES) {
        float nx = pnrm[t * 3 + 0], ny = pnrm[t * 3 + 1], nz = pnrm[t * 3 + 2];
        sNx[t] = nx; sNy[t] = ny; sNz[t] = nz;
        sOf[t] = pcen[t * 3 + 0] * nx + pcen[t * 3 + 1] * ny + pcen[t * 3 + 2] * nz;
        sMnx[t] = pmin[t * 3 + 0]; sMny[t] = pmin[t * 3 + 1]; sMnz[t] = pmin[t * 3 + 2];
        sMxx[t] = pmax[t * 3 + 0]; sMxy[t] = pmax[t * 3 + 1]; sMxz[t] = pmax[t * 3 + 2];
    }
    {
        float cx = centers[0], cy = centers[1], cz = centers[2];
        for (int i = t; i < PB; i += BTH) {
            size_t n = (size_t)n0 + i;
            sCx[i] = xyz[n * 3 + 0] + cx;
            sCy[i] = xyz[n * 3 + 1] + cy;
            sCz[i] = xyz[n * 3 + 2] + cz;
            sS[i]  = g_scores[n];
        }
    }
    __syncthreads();

    float* outS   = out;
    float* outM   = out + (size_t)NPLANES * NPTS;
    float* outOn  = out + 2 * (size_t)NPLANES * NPTS;
    float* outOff = out + 3 * (size_t)NPLANES * NPTS;
    float* featOn  = out + 4 * (size_t)NPLANES * NPTS;
    float* featOff = featOn + NPLANES * D;

    const int nlb = t * 4;          // this thread's 4 contiguous points
    const int dlo = lane * 2;       // this lane's 2 pooled channels

    for (int p = 0; p < NPLANES; p++) {
        float nx = sNx[p], ny = sNy[p], nz = sNz[p], of = sOf[p];
        float mnx = sMnx[p], mny = sMny[p], mnz = sMnz[p];
        float mxx = sMxx[p], mxy = sMxy[p], mxz = sMxz[p];

        unsigned onb = 0, offb = 0;
        float4 vS, vM, vOn, vOff;
        float* pS = &vS.x; float* pM = &vM.x; float* pOn = &vOn.x; float* pOff = &vOff.x;
#pragma unroll
        for (int i = 0; i < 4; i++) {
            int nl = nlb + i;
            float px = sCx[nl], py = sCy[nl], pz = sCz[nl];
            float dist = fabsf(px * nx + py * ny + pz * nz - of);
            bool okx = (mxx == 0.f) || (px >= mnx && px < mxx);
            bool oky = (mxy == 0.f) || (py >= mny && py < mxy);
            bool okz = (mxz == 0.f) || (pz >= mnz && pz < mxz);
            bool m = okx && oky && okz && (dist < 0.1f);
            float s = sS[nl];
            bool on = m && (s > 0.f);
            bool off = m && !(s > 0.f);
            pS[i]   = m ? s : 0.f;
            pM[i]   = m ? 1.f : 0.f;
            pOn[i]  = on ? 1.f : 0.f;
            pOff[i] = off ? 1.f : 0.f;
            onb  |= (unsigned)on  << i;
            offb |= (unsigned)off << i;
        }
        size_t o = (size_t)p * NPTS + n0 + nlb;
        *(float4*)&outS[o]   = vS;
        *(float4*)&outM[o]   = vM;
        *(float4*)&outOn[o]  = vOn;
        *(float4*)&outOff[o] = vOff;

        // warp-cooperative masked max-pool over h2 (post-ReLU, >= 0)
        float a0 = 0.f, a1 = 0.f, b0 = 0.f, b1 = 0.f;
#pragma unroll
        for (int i = 0; i < 4; i++) {
            unsigned bal = __ballot_sync(0xffffffffu, (onb >> i) & 1u);
            while (bal) {
                int src = __ffs(bal) - 1; bal &= bal - 1;
                size_t n = (size_t)n0 + (warp * 32 + src) * 4 + i;
                float2 v = *(const float2*)&g_h2[n * D + dlo];
                a0 = fmaxf(a0, v.x); a1 = fmaxf(a1, v.y);
            }
            bal = __ballot_sync(0xffffffffu, (offb >> i) & 1u);
            while (bal) {
                int src = __ffs(bal) - 1; bal &= bal - 1;
                size_t n = (size_t)n0 + (warp * 32 + src) * 4 + i;
                float2 v = *(const float2*)&g_h2[n * D + dlo];
                b0 = fmaxf(b0, v.x); b1 = fmaxf(b1, v.y);
            }
        }
        sRed[warp * 64 + dlo] = a0;       sRed[warp * 64 + dlo + 1] = a1;
        sRed[512 + warp * 64 + dlo] = b0; sRed[512 + warp * 64 + dlo + 1] = b1;
        __syncthreads();
        if (t < 128) {
            int which = t >> 6;           // 0 = on, 1 = off
            int d = t & 63;
            const float* base = sRed + which * 512;
            float v = 0.f;
#pragma unroll
            for (int w = 0; w < 8; w++) v = fmaxf(v, base[w * 64 + d]);
            if (v > 0.f) {                // atomicMax on int == float max for vals >= 0
                float* dst = which ? featOff : featOn;
                atomicMax((int*)&dst[p * D + d], __float_as_int(v));
            }
        }
        __syncthreads();
    }
}

// ---------------------------------------------------------------------------
extern "C" void kernel_launch(void* const* d_in, const int* in_sizes, int n_in,
                              void* d_out, int out_size) {
    (void)in_sizes; (void)n_in; (void)out_size;
    const float* feature  = (const float*)d_in[0];
    const float* fgeo     = (const float*)d_in[1];
    const float* xyz      = (const float*)d_in[2];
    const float* centers  = (const float*)d_in[3];
    const float* pcen     = (const float*)d_in[4];
    const float* pnrm     = (const float*)d_in[5];
    const float* pmin     = (const float*)d_in[6];
    const float* pmax     = (const float*)d_in[7];
    const float* w1 = (const float*)d_in[8];  const float* b1 = (const float*)d_in[9];
    const float* g1 = (const float*)d_in[10]; const float* be1 = (const float*)d_in[11];
    const float* m1 = (const float*)d_in[12]; const float* v1 = (const float*)d_in[13];
    const float* w2 = (const float*)d_in[14]; const float* b2 = (const float*)d_in[15];
    const float* g2 = (const float*)d_in[16]; const float* be2 = (const float*)d_in[17];
    const float* m2 = (const float*)d_in[18]; const float* v2 = (const float*)d_in[19];
    const float* w3 = (const float*)d_in[20]; const float* b3 = (const float*)d_in[21];
    float* out = (float*)d_out;

    cudaFuncSetAttribute(mlp_kernel, cudaFuncAttributeMaxDynamicSharedMemorySize,
                         (int)SMEM_A_BYTES);

    // zero the pooled-feature region (atomicMax targets)
    cudaMemsetAsync(out + 4 * (size_t)NPLANES * NPTS, 0,
                    2 * (size_t)NPLANES * D * sizeof(float));

    mlp_kernel<<<NPTS / BM, ATH, SMEM_A_BYTES>>>(
        feature, fgeo, w1, b1, g1, be1, m1, v1,
        w2, b2, g2, be2, m2, v2, w3, b3);

    mask_pool_kernel<<<NPTS / PB, BTH>>>(xyz, centers, pcen, pnrm, pmin, pmax, out);
}

// round 14
// speedup vs baseline: 1.3027x; 1.3027x over previous
#include <cuda_runtime.h>
#include <cuda_bf16.h>
#include <cstdint>
#include <cstddef>

#define NPTS 262144
#define NPLANES 128
#define D 64
#define TWOD 128

typedef unsigned long long u64;
typedef unsigned int u32;

// scratch (allocation-free rule: __device__ globals)
__device__ float g_h2[(size_t)NPTS * D];     // post-ReLU fc2 features, [N][64]
__device__ float g_scores[NPTS];             // post-ReLU fc3 scores
// pre-split weights (bf16 hi/lo, packed pairs along k), [n][k] layout
__device__ u32 g_w1hi[64 * 64], g_w1lo[64 * 64];   // w1T: n=64, k=128 (64 pairs)
__device__ u32 g_w2hi[64 * 32], g_w2lo[64 * 32];   // w2T: n=64, k=64  (32 pairs)
__device__ float g_consts[384];                    // s1,t1,s2,t2,w3,[320]=b3

__device__ __forceinline__ void bf16_split(float f, __nv_bfloat16& hi, __nv_bfloat16& lo) {
    hi = __float2bfloat16(f);
    lo = __float2bfloat16(f - __bfloat162float(hi));
}
__device__ __forceinline__ u32 pack2(__nv_bfloat16 a, __nv_bfloat16 b) {
    __nv_bfloat162 t; t.x = a; t.y = b;
    return *reinterpret_cast<u32*>(&t);
}

#define MMA16816(c, a0, a1, a2, a3, b0, b1) \
    asm volatile("mma.sync.aligned.m16n8k16.row.col.f32.bf16.bf16.f32 " \
        "{%0,%1,%2,%3}, {%4,%5,%6,%7}, {%8,%9}, {%0,%1,%2,%3};" \
        : "+f"((c)[0]), "+f"((c)[1]), "+f"((c)[2]), "+f"((c)[3]) \
        : "r"(a0), "r"(a1), "r"(a2), "r"(a3), "r"(b0), "r"(b1))

// ---------------------------------------------------------------------------
// Prep kernel: fold BN, transpose+split weights to bf16 hi/lo. Runs once, tiny.
// ---------------------------------------------------------------------------
__global__ void prep_kernel(const float* __restrict__ w1, const float* __restrict__ b1,
                            const float* __restrict__ g1, const float* __restrict__ be1,
                            const float* __restrict__ m1, const float* __restrict__ v1,
                            const float* __restrict__ w2, const float* __restrict__ b2,
                            const float* __restrict__ g2, const float* __restrict__ be2,
                            const float* __restrict__ m2, const float* __restrict__ v2,
                            const float* __restrict__ w3, const float* __restrict__ b3)
{
    int t = threadIdx.x;
    if (t < 64) {
        float sc = g1[t] * rsqrtf(v1[t] + 1e-5f);
        g_consts[t]       = sc;
        g_consts[64 + t]  = (b1[t] - m1[t]) * sc + be1[t];
        float sc2 = g2[t] * rsqrtf(v2[t] + 1e-5f);
        g_consts[128 + t] = sc2;
        g_consts[192 + t] = (b2[t] - m2[t]) * sc2 + be2[t];
        g_consts[256 + t] = w3[t];
    }
    if (t == 64) g_consts[320] = b3[0];
    for (int idx = t; idx < 64 * 64; idx += blockDim.x) {
        int n = idx >> 6, kp = idx & 63;
        float f0 = w1[(size_t)(2 * kp) * D + n];
        float f1 = w1[(size_t)(2 * kp + 1) * D + n];
        __nv_bfloat16 h0, l0, h1, l1;
        bf16_split(f0, h0, l0); bf16_split(f1, h1, l1);
        g_w1hi[n * 64 + kp] = pack2(h0, h1);
        g_w1lo[n * 64 + kp] = pack2(l0, l1);
    }
    for (int idx = t; idx < 64 * 32; idx += blockDim.x) {
        int n = idx >> 5, kp = idx & 31;
        float f0 = w2[(size_t)(2 * kp) * D + n];
        float f1 = w2[(size_t)(2 * kp + 1) * D + n];
        __nv_bfloat16 h0, l0, h1, l1;
        bf16_split(f0, h0, l0); bf16_split(f1, h1, l1);
        g_w2hi[n * 32 + kp] = pack2(h0, h1);
        g_w2lo[n * 32 + kp] = pack2(l0, l1);
    }
}

// ---------------------------------------------------------------------------
// Kernel A: fused MLP via mma.sync bf16 HMMA, 3-term split-fp32.
// 64 points/block, 128 threads (4 warps x 16 points). fp32 reg accumulators.
// ---------------------------------------------------------------------------
constexpr int TBM = 64;
constexpr int TTH = 128;
// smem word strides (u32 units): A1/B1 rows 68 (=136 bf16), A2/B2 rows 36 (=72 bf16)
constexpr int OFF_CONST = 0;                       // 384 floats = 1536 B
constexpr int OFF_A1HI  = 1536;                    // 64*68*4 = 17408 B
constexpr int OFF_A1LO  = OFF_A1HI + 17408;
constexpr int OFF_B1HI  = OFF_A1LO + 17408;
constexpr int OFF_B1LO  = OFF_B1HI + 17408;
constexpr int OFF_B2HI  = OFF_B1LO + 17408;        // 64*36*4 = 9216 B
constexpr int OFF_B2LO  = OFF_B2HI + 9216;
constexpr int SMEM_MLP_BYTES = OFF_B2LO + 9216;    // 89600 B
// A2 (h1 split) reuses A1 region
constexpr int OFF_A2HI  = OFF_A1HI;
constexpr int OFF_A2LO  = OFF_A1HI + 9216;

__global__ void __launch_bounds__(TTH, 2)
mlp_mma_kernel(const float* __restrict__ feat, const float* __restrict__ fgeo)
{
    extern __shared__ char smem[];
    const int t = threadIdx.x;
    const int warp = t >> 5, lane = t & 31;
    const int gr = lane >> 2, tc = lane & 3;
    const int n0 = blockIdx.x * TBM;

    float* sConst = (float*)(smem + OFF_CONST);
    u32* A1hi = (u32*)(smem + OFF_A1HI);
    u32* A1lo = (u32*)(smem + OFF_A1LO);
    u32* B1hi = (u32*)(smem + OFF_B1HI);
    u32* B1lo = (u32*)(smem + OFF_B1LO);
    u32* B2hi = (u32*)(smem + OFF_B2HI);
    u32* B2lo = (u32*)(smem + OFF_B2LO);
    u32* A2hi = (u32*)(smem + OFF_A2HI);
    u32* A2lo = (u32*)(smem + OFF_A2LO);

    // constants + weight tiles into smem
    for (int i = t; i < 384; i += TTH) sConst[i] = g_consts[i];
    for (int idx = t; idx < 64 * 64; idx += TTH) {
        int n = idx >> 6, kp = idx & 63;
        B1hi[n * 68 + kp] = g_w1hi[idx];
        B1lo[n * 68 + kp] = g_w1lo[idx];
    }
    for (int idx = t; idx < 64 * 32; idx += TTH) {
        int n = idx >> 5, kp = idx & 31;
        B2hi[n * 36 + kp] = g_w2hi[idx];
        B2lo[n * 36 + kp] = g_w2lo[idx];
    }
    // features: load fp32, split, store packed bf16 pairs (row p, pair kp)
    for (int idx = t; idx < TBM * 64; idx += TTH) {
        int p = idx >> 6, kp = idx & 63;
        int k = kp * 2;
        const float* src = (k < D) ? &feat[(size_t)(n0 + p) * D + k]
                                   : &fgeo[(size_t)(n0 + p) * D + (k - D)];
        float2 v = *(const float2*)src;
        __nv_bfloat16 h0, l0, h1, l1;
        bf16_split(v.x, h0, l0); bf16_split(v.y, h1, l1);
        A1hi[p * 68 + kp] = pack2(h0, h1);
        A1lo[p * 68 + kp] = pack2(l0, l1);
    }
    __syncthreads();

    const int rowA = warp * 16 + gr;      // this thread's low row (local point)

    // ---- fc1: [64 x 128] @ [128 x 64], 8 k-tiles, 8 n-tiles, 3 terms ----
    float c1[8][4];
#pragma unroll
    for (int nt = 0; nt < 8; nt++)
#pragma unroll
        for (int j = 0; j < 4; j++) c1[nt][j] = 0.f;

#pragma unroll
    for (int kt = 0; kt < 8; kt++) {
        int kw = kt * 8 + tc;
        u32 ah0 = A1hi[rowA * 68 + kw],       ah1 = A1hi[(rowA + 8) * 68 + kw];
        u32 ah2 = A1hi[rowA * 68 + kw + 4],   ah3 = A1hi[(rowA + 8) * 68 + kw + 4];
        u32 al0 = A1lo[rowA * 68 + kw],       al1 = A1lo[(rowA + 8) * 68 + kw];
        u32 al2 = A1lo[rowA * 68 + kw + 4],   al3 = A1lo[(rowA + 8) * 68 + kw + 4];
#pragma unroll
        for (int nt = 0; nt < 8; nt++) {
            int rb = (nt * 8 + gr) * 68 + kw;
            u32 bh0 = B1hi[rb], bh1 = B1hi[rb + 4];
            u32 bl0 = B1lo[rb], bl1 = B1lo[rb + 4];
            MMA16816(c1[nt], ah0, ah1, ah2, ah3, bh0, bh1);
            MMA16816(c1[nt], ah0, ah1, ah2, ah3, bl0, bl1);
            MMA16816(c1[nt], al0, al1, al2, al3, bh0, bh1);
        }
    }
    __syncthreads();   // all warps done reading A1 before A2 overwrites it

    // ---- bn1 + relu, split, store h1 as A2 tiles ----
#pragma unroll
    for (int nt = 0; nt < 8; nt++) {
        int col = nt * 8 + 2 * tc;
        float s0 = sConst[col], s1c = sConst[col + 1];
        float t0 = sConst[64 + col], t1c = sConst[64 + col + 1];
        float h00 = fmaxf(c1[nt][0] * s0 + t0, 0.f);
        float h01 = fmaxf(c1[nt][1] * s1c + t1c, 0.f);
        float h10 = fmaxf(c1[nt][2] * s0 + t0, 0.f);
        float h11 = fmaxf(c1[nt][3] * s1c + t1c, 0.f);
        __nv_bfloat16 a, b;
        __nv_bfloat16 hh, hl;
        int w0 = rowA * 36 + nt * 4 + tc;
        int w1i = (rowA + 8) * 36 + nt * 4 + tc;
        bf16_split(h00, a, hh); bf16_split(h01, b, hl);
        A2hi[w0] = pack2(a, b);  A2lo[w0] = pack2(hh, hl);
        bf16_split(h10, a, hh); bf16_split(h11, b, hl);
        A2hi[w1i] = pack2(a, b); A2lo[w1i] = pack2(hh, hl);
    }
    __syncthreads();

    // ---- fc2: [64 x 64] @ [64 x 64], 4 k-tiles, 8 n-tiles, 3 terms ----
    float c2[8][4];
#pragma unroll
    for (int nt = 0; nt < 8; nt++)
#pragma unroll
        for (int j = 0; j < 4; j++) c2[nt][j] = 0.f;

#pragma unroll
    for (int kt = 0; kt < 4; kt++) {
        int kw = kt * 8 + tc;
        u32 ah0 = A2hi[rowA * 36 + kw],       ah1 = A2hi[(rowA + 8) * 36 + kw];
        u32 ah2 = A2hi[rowA * 36 + kw + 4],   ah3 = A2hi[(rowA + 8) * 36 + kw + 4];
        u32 al0 = A2lo[rowA * 36 + kw],       al1 = A2lo[(rowA + 8) * 36 + kw];
        u32 al2 = A2lo[rowA * 36 + kw + 4],   al3 = A2lo[(rowA + 8) * 36 + kw + 4];
#pragma unroll
        for (int nt = 0; nt < 8; nt++) {
            int rb = (nt * 8 + gr) * 36 + kw;
            u32 bh0 = B2hi[rb], bh1 = B2hi[rb + 4];
            u32 bl0 = B2lo[rb], bl1 = B2lo[rb + 4];
            MMA16816(c2[nt], ah0, ah1, ah2, ah3, bh0, bh1);
            MMA16816(c2[nt], ah0, ah1, ah2, ah3, bl0, bl1);
            MMA16816(c2[nt], al0, al1, al2, al3, bh0, bh1);
        }
    }

    // ---- bn2 + relu -> h2 (direct global store) + fc3 score ----
    float scLo = 0.f, scHi = 0.f;
#pragma unroll
    for (int nt = 0; nt < 8; nt++) {
        int col = nt * 8 + 2 * tc;
        float s0 = sConst[128 + col], s1c = sConst[128 + col + 1];
        float t0 = sConst[192 + col], t1c = sConst[192 + col + 1];
        float w30 = sConst[256 + col], w31 = sConst[256 + col + 1];
        float h00 = fmaxf(c2[nt][0] * s0 + t0, 0.f);
        float h01 = fmaxf(c2[nt][1] * s1c + t1c, 0.f);
        float h10 = fmaxf(c2[nt][2] * s0 + t0, 0.f);
        float h11 = fmaxf(c2[nt][3] * s1c + t1c, 0.f);
        *(float2*)&g_h2[(size_t)(n0 + rowA) * D + col]     = make_float2(h00, h01);
        *(float2*)&g_h2[(size_t)(n0 + rowA + 8) * D + col] = make_float2(h10, h11);
        scLo += h00 * w30 + h01 * w31;
        scHi += h10 * w30 + h11 * w31;
    }
    scLo += __shfl_xor_sync(0xffffffffu, scLo, 1);
    scLo += __shfl_xor_sync(0xffffffffu, scLo, 2);
    scHi += __shfl_xor_sync(0xffffffffu, scHi, 1);
    scHi += __shfl_xor_sync(0xffffffffu, scHi, 2);
    if (tc == 0) {
        float bb = sConst[320];
        g_scores[n0 + rowA]     = fmaxf(scLo + bb, 0.f);
        g_scores[n0 + rowA + 8] = fmaxf(scHi + bb, 0.f);
    }
}

// ---------------------------------------------------------------------------
// Kernel B: per-plane masks + output streaming + masked max-pool.
// gridDim.y = PSPLIT partitions the plane loop (occupancy fix: 256 -> 1024 blocks).
// ---------------------------------------------------------------------------
constexpr int BTH = 256;
constexpr int PB  = 1024;
constexpr int PSPLIT = 4;
constexpr int PPG = NPLANES / PSPLIT;   // 32 planes per block

__global__ void __launch_bounds__(BTH)
mask_pool_kernel(const float* __restrict__ xyz, const float* __restrict__ centers,
                 const float* __restrict__ pcen, const float* __restrict__ pnrm,
                 const float* __restrict__ pmin, const float* __restrict__ pmax,
                 float* __restrict__ out)
{
    __shared__ float sNx[PPG], sNy[PPG], sNz[PPG], sOf[PPG];
    __shared__ float sMnx[PPG], sMny[PPG], sMnz[PPG];
    __shared__ float sMxx[PPG], sMxy[PPG], sMxz[PPG];
    __shared__ float sCx[PB], sCy[PB], sCz[PB], sS[PB];
    __shared__ float sRed[2 * 8 * 64];

    const int t = threadIdx.x;
    const int warp = t >> 5, lane = t & 31;
    const int n0 = blockIdx.x * PB;
    const int pbase = blockIdx.y * PPG;

    if (t < PPG) {
        int pg = pbase + t;
        float nx = pnrm[pg * 3 + 0], ny = pnrm[pg * 3 + 1], nz = pnrm[pg * 3 + 2];
        sNx[t] = nx; sNy[t] = ny; sNz[t] = nz;
        sOf[t] = pcen[pg * 3 + 0] * nx + pcen[pg * 3 + 1] * ny + pcen[pg * 3 + 2] * nz;
        sMnx[t] = pmin[pg * 3 + 0]; sMny[t] = pmin[pg * 3 + 1]; sMnz[t] = pmin[pg * 3 + 2];
        sMxx[t] = pmax[pg * 3 + 0]; sMxy[t] = pmax[pg * 3 + 1]; sMxz[t] = pmax[pg * 3 + 2];
    }
    {
        float cx = centers[0], cy = centers[1], cz = centers[2];
        for (int i = t; i < PB; i += BTH) {
            size_t n = (size_t)n0 + i;
            sCx[i] = xyz[n * 3 + 0] + cx;
            sCy[i] = xyz[n * 3 + 1] + cy;
            sCz[i] = xyz[n * 3 + 2] + cz;
            sS[i]  = g_scores[n];
        }
    }
    __syncthreads();

    float* outS   = out;
    float* outM   = out + (size_t)NPLANES * NPTS;
    float* outOn  = out + 2 * (size_t)NPLANES * NPTS;
    float* outOff = out + 3 * (size_t)NPLANES * NPTS;
    float* featOn  = out + 4 * (size_t)NPLANES * NPTS;
    float* featOff = featOn + NPLANES * D;

    const int nlb = t * 4;
    const int dlo = lane * 2;

    for (int pl = 0; pl < PPG; pl++) {
        const int p = pbase + pl;
        float nx = sNx[pl], ny = sNy[pl], nz = sNz[pl], of = sOf[pl];
        float mnx = sMnx[pl], mny = sMny[pl], mnz = sMnz[pl];
        float mxx = sMxx[pl], mxy = sMxy[pl], mxz = sMxz[pl];

        unsigned onb = 0, offb = 0;
        float4 vS, vM, vOn, vOff;
        float* pS = &vS.x; float* pM = &vM.x; float* pOn = &vOn.x; float* pOff = &vOff.x;
#pragma unroll
        for (int i = 0; i < 4; i++) {
            int nl = nlb + i;
            float px = sCx[nl], py = sCy[nl], pz = sCz[nl];
            float dist = fabsf(px * nx + py * ny + pz * nz - of);
            bool okx = (mxx == 0.f) || (px >= mnx && px < mxx);
            bool oky = (mxy == 0.f) || (py >= mny && py < mxy);
            bool okz = (mxz == 0.f) || (pz >= mnz && pz < mxz);
            bool m = okx && oky && okz && (dist < 0.1f);
            float s = sS[nl];
            bool on = m && (s > 0.f);
            bool off = m && !(s > 0.f);
            pS[i]   = m ? s : 0.f;
            pM[i]   = m ? 1.f : 0.f;
            pOn[i]  = on ? 1.f : 0.f;
            pOff[i] = off ? 1.f : 0.f;
            onb  |= (unsigned)on  << i;
            offb |= (unsigned)off << i;
        }
        size_t o = (size_t)p * NPTS + n0 + nlb;
        *(float4*)&outS[o]   = vS;
        *(float4*)&outM[o]   = vM;
        *(float4*)&outOn[o]  = vOn;
        *(float4*)&outOff[o] = vOff;

        float a0 = 0.f, a1 = 0.f, b0 = 0.f, b1 = 0.f;
#pragma unroll
        for (int i = 0; i < 4; i++) {
            unsigned bal = __ballot_sync(0xffffffffu, (onb >> i) & 1u);
            while (bal) {
                int src = __ffs(bal) - 1; bal &= bal - 1;
                size_t n = (size_t)n0 + (warp * 32 + src) * 4 + i;
                float2 v = *(const float2*)&g_h2[n * D + dlo];
                a0 = fmaxf(a0, v.x); a1 = fmaxf(a1, v.y);
            }
            bal = __ballot_sync(0xffffffffu, (offb >> i) & 1u);
            while (bal) {
                int src = __ffs(bal) - 1; bal &= bal - 1;
                size_t n = (size_t)n0 + (warp * 32 + src) * 4 + i;
                float2 v = *(const float2*)&g_h2[n * D + dlo];
                b0 = fmaxf(b0, v.x); b1 = fmaxf(b1, v.y);
            }
        }
        sRed[warp * 64 + dlo] = a0;       sRed[warp * 64 + dlo + 1] = a1;
        sRed[512 + warp * 64 + dlo] = b0; sRed[512 + warp * 64 + dlo + 1] = b1;
        __syncthreads();
        if (t < 128) {
            int which = t >> 6;
            int d = t & 63;
            const float* base = sRed + which * 512;
            float v = 0.f;
#pragma unroll
            for (int w = 0; w < 8; w++) v = fmaxf(v, base[w * 64 + d]);
            if (v > 0.f) {
                float* dst = which ? featOff : featOn;
                atomicMax((int*)&dst[p * D + d], __float_as_int(v));
            }
        }
        __syncthreads();
    }
}

// ---------------------------------------------------------------------------
extern "C" void kernel_launch(void* const* d_in, const int* in_sizes, int n_in,
                              void* d_out, int out_size) {
    (void)in_sizes; (void)n_in; (void)out_size;
    const float* feature  = (const float*)d_in[0];
    const float* fgeo     = (const float*)d_in[1];
    const float* xyz      = (const float*)d_in[2];
    const float* centers  = (const float*)d_in[3];
    const float* pcen     = (const float*)d_in[4];
    const float* pnrm     = (const float*)d_in[5];
    const float* pmin     = (const float*)d_in[6];
    const float* pmax     = (const float*)d_in[7];
    const float* w1 = (const float*)d_in[8];  const float* b1 = (const float*)d_in[9];
    const float* g1 = (const float*)d_in[10]; const float* be1 = (const float*)d_in[11];
    const float* m1 = (const float*)d_in[12]; const float* v1 = (const float*)d_in[13];
    const float* w2 = (const float*)d_in[14]; const float* b2 = (const float*)d_in[15];
    const float* g2 = (const float*)d_in[16]; const float* be2 = (const float*)d_in[17];
    const float* m2 = (const float*)d_in[18]; const float* v2 = (const float*)d_in[19];
    const float* w3 = (const float*)d_in[20]; const float* b3 = (const float*)d_in[21];
    float* out = (float*)d_out;

    cudaFuncSetAttribute(mlp_mma_kernel, cudaFuncAttributeMaxDynamicSharedMemorySize,
                         SMEM_MLP_BYTES);

    // zero the pooled-feature region (atomicMax targets)
    cudaMemsetAsync(out + 4 * (size_t)NPLANES * NPTS, 0,
                    2 * (size_t)NPLANES * D * sizeof(float));

    prep_kernel<<<1, 256>>>(w1, b1, g1, be1, m1, v1,
                            w2, b2, g2, be2, m2, v2, w3, b3);

    mlp_mma_kernel<<<NPTS / TBM, TTH, SMEM_MLP_BYTES>>>(feature, fgeo);

    dim3 gridB(NPTS / PB, PSPLIT);
    mask_pool_kernel<<<gridB, BTH>>>(xyz, centers, pcen, pnrm, pmin, pmax, out);
}